// round 15
// baseline (speedup 1.0000x reference)
#include <cuda_runtime.h>

// Problem constants (fixed by the reference: B=2048, S=128, N=B*S).
#define B_ROWS   2048
#define S_ITEMS  128
#define N_ITEMS  (B_ROWS * S_ITEMS)
#define WARPS_PB 8                       // warps per block (1 row per warp)
#define NBLOCKS  (B_ROWS / WARPS_PB)     // 256 blocks
#define FX_SCALE 1048576.0               // 2^20 fixed-point scale

// Lines of 128B per array slice prefetched by each block (1MB / 256 blocks).
#define PF_LINES 32

// Scratch: packed accumulator. bits[0,48) = fixed-point sum (partials >= 0),
// bits[48,64) = contributing-block count. Zero-initialized.
__device__ unsigned long long g_acc;

// Analytic simplification of the reference (valid because y is one-hot per
// assortment row, which setup_inputs guarantees):
//   result = (1/B) * sum_b [ s_b + log(S - rank_b) ]
// where chosen_b = xa at the one-hot position, s_b = sum relu(xa - chosen),
// rank_b = stable ascending rank of chosen (ties broken by position).
//
// New this round: at kernel start every block issues prefetch.global.L2 for a
// dense slice of x and y (chip-wide this streams both arrays into L2,
// coalesced). The scattered gathers depend on the assortment index load (a
// ~600cyc cold miss), which exactly hides the prefetch fill latency — so the
// gathers land as L2 hits instead of random 32B-sector DRAM misses.
// Tail: ONE packed 64-bit atomicAdd per block; the returned old value is both
// ticket and running sum (integer adds commute -> bit-deterministic).
__global__ void __launch_bounds__(256) exp_loss_fused(
    const float* __restrict__ x,
    const float* __restrict__ y,
    const int*   __restrict__ assort,
    float*       __restrict__ out)
{
    const unsigned FULL = 0xffffffffu;
    const int tid    = threadIdx.x;
    const int lane   = tid & 31;
    const int warpid = tid >> 5;                        // 0..7
    const int row    = blockIdx.x * WARPS_PB + warpid;  // 0..2047

    // ---- step 0: dense L2 prefetch of x and y (fire-and-forget) ----
    // threads 0..31 cover 32 lines of x, threads 32..63 cover 32 lines of y.
    if (tid < 2 * PF_LINES) {
        const char* base = (tid < PF_LINES) ? (const char*)x : (const char*)y;
        int line = blockIdx.x * PF_LINES + (tid & (PF_LINES - 1));
        asm volatile("prefetch.global.L2 [%0];" :: "l"(base + (size_t)line * 128));
    }

    // ---- step 1: coalesced index load (cold miss ~600cyc hides the fills) ----
    const int4* arow = reinterpret_cast<const int4*>(assort + row * S_ITEMS);
    int4 a = __ldg(arow + lane);
    int idx4[4] = {a.x, a.y, a.z, a.w};

    // ---- step 2: 8 scattered gathers, now (mostly) L2 hits ----
    float xv[4], yv[4];
#pragma unroll
    for (int i = 0; i < 4; i++) {
        xv[i] = __ldg(x + idx4[i]);
        yv[i] = __ldg(y + idx4[i]);
    }

    // Locate the one-hot item: one ballot + 2 shfl broadcasts.
    float lch  = 0.0f;
    int   lpos = -1;
#pragma unroll
    for (int i = 0; i < 4; i++) {
        lch += xv[i] * yv[i];              // exact: other terms are +-0
        if (yv[i] != 0.0f) lpos = lane * 4 + i;
    }
    unsigned bal = __ballot_sync(FULL, lpos >= 0);
    int   src = __ffs(bal) - 1;            // exactly one lane holds the item
    float ch  = __shfl_sync(FULL, lch,  src);
    int   pos = __shfl_sync(FULL, lpos, src);

    // s = sum relu(xa - chosen);  rank = stable ascending rank of chosen.
    float sv = 0.0f;
    int   rk = 0;
#pragma unroll
    for (int i = 0; i < 4; i++) {
        sv += fmaxf(xv[i] - ch, 0.0f);
        int gi = lane * 4 + i;
        rk += (xv[i] < ch) || (xv[i] == ch && gi < pos);
    }
#pragma unroll
    for (int o = 16; o; o >>= 1)
        sv += __shfl_xor_sync(FULL, sv, o);
    rk = __reduce_add_sync(FULL, rk);      // REDUX.SUM

    // ---- block fold: 8 warp values -> ONE packed atomic ----
    __shared__ float warpval[WARPS_PB];
    if (lane == 0)
        warpval[warpid] = sv + __logf((float)(S_ITEMS - rk));
    __syncthreads();

    if (tid == 0) {
        double acc = 0.0;
#pragma unroll
        for (int i = 0; i < WARPS_PB; i++) acc += (double)warpval[i];
        // acc >= 0 always (s >= 0, log(S-rank) >= log(1) = 0).
        unsigned long long fx = (unsigned long long)llrint(acc * FX_SCALE);
        unsigned long long old = atomicAdd(&g_acc, fx | (1ull << 48));
        if ((old >> 48) == (unsigned long long)(NBLOCKS - 1)) {
            unsigned long long total = (old & 0xFFFFFFFFFFFFull) + fx;
            out[0] = (float)((double)total / FX_SCALE / (double)B_ROWS);
            g_acc = 0ull;                  // reset for next graph replay
        }
    }
}

extern "C" void kernel_launch(void* const* d_in, const int* in_sizes, int n_in,
                              void* d_out, int out_size)
{
    const float* x      = (const float*)d_in[0];
    const float* y      = (const float*)d_in[1];
    const int*   assort = (const int*)d_in[2];

    exp_loss_fused<<<NBLOCKS, 256>>>(x, y, assort, (float*)d_out);
}

// round 16
// speedup vs baseline: 1.1581x; 1.1581x over previous
#include <cuda_runtime.h>

// Problem constants (fixed by the reference: B=2048, S=128, N=B*S).
#define B_ROWS   2048
#define S_ITEMS  128
#define WARPS_PB 8                       // warps per block (1 row per warp)
#define NBLOCKS  (B_ROWS / WARPS_PB)     // 256 blocks
#define FX_SCALE 1048576.0f              // 2^20 fixed-point scale

// Scratch (no device allocation allowed -> __device__ globals, zero-init).
__device__ unsigned long long g_acc;     // fixed-point deterministic accumulator
__device__ unsigned int       g_ticket;  // completion ticket

// Analytic simplification of the reference (valid because y is one-hot per
// assortment row, which setup_inputs guarantees):
//   result = (1/B) * sum_b [ s_b + log(S - rank_b) ]
// where
//   chosen_b = xa at the one-hot position,
//   s_b      = sum_k relu(xa[b,k] - chosen_b),
//   rank_b   = stable ascending rank of chosen within the row
//            = #{k: xa<chosen} + #{k<pos: xa==chosen}.
//
// Final configuration, chosen from 14 rounds of measurement:
//  * 256 blocks x 256 threads, row-per-warp, 4 items/lane (1 int4 index load
//    + 8 batched scattered gathers): best-measured shape (7.17us kernel, 3x).
//  * Fixed-point int64 atomic fold (integer adds commute -> bit-deterministic)
//    + ticket; single kernel (any 2nd kernel costs ~4.9us fixed floor here).
//  * Falsified levers (all neutral +-0.4us): occupancy 17-84%, per-thread MLP
//    2-8, halved wavefronts, 1 vs 2 waves, grid barriers (+3us), kernel
//    splits (+2-5us), packed single atomic, spread tickets, L2 prefetch,
//    fine/coarse scheduling. Kernel marginal work ~2.3us over a ~5us
//    environment floor.
__global__ void __launch_bounds__(256) exp_loss_fused(
    const float* __restrict__ x,
    const float* __restrict__ y,
    const int*   __restrict__ assort,
    float*       __restrict__ out)
{
    const unsigned FULL = 0xffffffffu;
    const int tid    = threadIdx.x;
    const int lane   = tid & 31;
    const int warpid = tid >> 5;                        // 0..7
    const int row    = blockIdx.x * WARPS_PB + warpid;  // 0..2047

    // ---- per-row: 1 int4 index load + 8 independent gathers, batched ----
    const int4* arow = reinterpret_cast<const int4*>(assort + row * S_ITEMS);
    int4 a = __ldg(arow + lane);
    int idx4[4] = {a.x, a.y, a.z, a.w};

    float xv[4], yv[4];
#pragma unroll
    for (int i = 0; i < 4; i++) {
        xv[i] = __ldg(x + idx4[i]);
        yv[i] = __ldg(y + idx4[i]);
    }

    // Locate the one-hot item: one ballot + 2 shfl broadcasts.
    float lch  = 0.0f;
    int   lpos = -1;
#pragma unroll
    for (int i = 0; i < 4; i++) {
        lch += xv[i] * yv[i];              // exact: other terms are +-0
        if (yv[i] != 0.0f) lpos = lane * 4 + i;
    }
    unsigned bal = __ballot_sync(FULL, lpos >= 0);
    int   src = __ffs(bal) - 1;            // exactly one lane holds the item
    float ch  = __shfl_sync(FULL, lch,  src);
    int   pos = __shfl_sync(FULL, lpos, src);

    // s = sum relu(xa - chosen);  rank = stable ascending rank of chosen.
    float sv = 0.0f;
    int   rk = 0;
#pragma unroll
    for (int i = 0; i < 4; i++) {
        sv += fmaxf(xv[i] - ch, 0.0f);
        int gi = lane * 4 + i;
        rk += (xv[i] < ch) || (xv[i] == ch && gi < pos);
    }
#pragma unroll
    for (int o = 16; o; o >>= 1)
        sv += __shfl_xor_sync(FULL, sv, o);
    rk = __reduce_add_sync(FULL, rk);      // REDUX.SUM

    // ---- block fold: 8 warp values, folded by warp 0 with shfl ----
    __shared__ float warpval[WARPS_PB];
    if (lane == 0)
        warpval[warpid] = sv + __logf((float)(S_ITEMS - rk));
    __syncthreads();

    if (warpid == 0) {
        float v = (lane < WARPS_PB) ? warpval[lane] : 0.0f;
#pragma unroll
        for (int o = 4; o; o >>= 1)
            v += __shfl_xor_sync(FULL, v, o);
        if (lane == 0) {
            // Per-block partial is >= 0 (s >= 0, log(S-rank) >= 0); 2^20
            // fixed point keeps the grid total < 2^40 and quantization
            // ~1e-7 relative — far inside the 1e-3 tolerance.
            unsigned long long fx =
                (unsigned long long)(long long)llrintf(v * FX_SCALE);
            // Returning atomic completes at L2 before the ticket atomic, so
            // the last ticket implies every block's value-add is visible.
            (void)atomicAdd(&g_acc, fx);
            unsigned int t = atomicAdd(&g_ticket, 1u);
            if (t == (unsigned)(NBLOCKS - 1)) {
                long long total = (long long)atomicAdd(&g_acc, 0ull);
                out[0] = (float)((double)total / (double)FX_SCALE
                                 / (double)B_ROWS);
                g_acc    = 0ull;           // reset for next graph replay
                g_ticket = 0u;
            }
        }
    }
}

extern "C" void kernel_launch(void* const* d_in, const int* in_sizes, int n_in,
                              void* d_out, int out_size)
{
    const float* x      = (const float*)d_in[0];
    const float* y      = (const float*)d_in[1];
    const int*   assort = (const int*)d_in[2];

    exp_loss_fused<<<NBLOCKS, 256>>>(x, y, assort, (float*)d_out);
}